// round 5
// baseline (speedup 1.0000x reference)
#include <cuda_runtime.h>
#include <cuda_bf16.h>

// points (B=4, C=84, H=512, W=512) fp32.
// probs = max over channels [0,80); 3x3 NMS, raster tie-break; out = points * mask.
//
// Fused single-pass kernel: per 16x64 tile, compute probs (tile + 1px halo) into
// SMEM, then mask + multiply, re-reading points from L2 (occupancy capped at
// 1 CTA/SM via dynamic-smem padding so the reuse window fits in L2).

constexpr int B_  = 4;
constexpr int C_  = 84;
constexpr int CM_ = 80;
constexpr int H_  = 512;
constexpr int W_  = 512;
constexpr int HW_  = H_ * W_;
constexpr int HW4_ = HW_ / 4;
constexpr int W4_  = W_ / 4;

constexpr int TH = 16;            // tile rows
constexpr int TW = 64;            // tile cols (16 float4)
constexpr int SPW = TW + 4;       // smem probs row stride (68)
constexpr int SMEM_PAD_BYTES = 120 * 1024;   // forces 1 CTA/SM (228KB carveout)

__global__ __launch_bounds__(256)
void nms_fused_kernel(const float* __restrict__ pts, float* __restrict__ out) {
    extern __shared__ float sp[];    // (TH+2) x SPW probs incl. halo

    const int tx = blockIdx.x;       // 0..7
    const int ty = blockIdx.y;       // 0..31
    const int b  = blockIdx.z;       // 0..3
    const int h0 = ty * TH;
    const int w0 = tx * TW;
    const int tid = threadIdx.x;
    const int r   = tid >> 4;        // 0..15  (tile row)
    const int c4  = tid & 15;        // 0..15  (float4 within row)

    const float* pb = pts + (size_t)b * C_ * HW_;

    // ---------- Phase 1a: interior probs, one float4 per thread ----------
    const int off4 = (h0 + r) * W4_ + (w0 >> 2) + c4;   // float4 index in plane
    {
        const float4* p4 = reinterpret_cast<const float4*>(pb) + off4;
        float4 m = p4[0];
        #pragma unroll 8
        for (int c = 1; c < CM_; c++) {
            float4 v = p4[c * HW4_];
            m.x = fmaxf(m.x, v.x);
            m.y = fmaxf(m.y, v.y);
            m.z = fmaxf(m.z, v.z);
            m.w = fmaxf(m.w, v.w);
        }
        float* d = sp + (r + 1) * SPW + 1 + c4 * 4;
        d[0] = m.x; d[1] = m.y; d[2] = m.z; d[3] = m.w;
    }

    // ---------- Phase 1b: halo probs (scalar; 164 px per tile) ----------
    // 0..65   : top row    (hh = h0-1,  ww = w0-1 .. w0+64)
    // 66..131 : bottom row (hh = h0+TH)
    // 132..147: left col   (ww = w0-1,  hh = h0 .. h0+15)
    // 148..163: right col  (ww = w0+TW)
    if (tid < 164) {
        int hh, ww, si, sj;
        if (tid < 66)       { hh = h0 - 1;          ww = w0 - 1 + tid;        si = 0;         sj = tid;      }
        else if (tid < 132) { hh = h0 + TH;         ww = w0 - 1 + (tid - 66); si = TH + 1;    sj = tid - 66; }
        else if (tid < 148) { hh = h0 + (tid - 132); ww = w0 - 1;             si = tid - 131; sj = 0;        }
        else                { hh = h0 + (tid - 148); ww = w0 + TW;            si = tid - 147; sj = TW + 1;   }
        float m = 0.0f;   // zero-padding value (matches jnp.pad)
        if (hh >= 0 && hh < H_ && ww >= 0 && ww < W_) {
            const float* p = pb + hh * W_ + ww;
            m = p[0];
            #pragma unroll 8
            for (int c = 1; c < CM_; c++) m = fmaxf(m, p[c * HW_]);
        }
        sp[si * SPW + sj] = m;
    }
    __syncthreads();

    // ---------- Phase 2: mask ----------
    // center_idx = 4 in 3x3 raster order:
    //   strict >  for (-1,-1),(-1,0),(-1,+1),(0,-1)
    //   >=        for (0,+1),(+1,-1),(+1,0),(+1,+1)
    float mk[4];
    {
        const float* rr0 = sp + r * SPW + c4 * 4;   // row above, starting at col-1
        const float* rr1 = rr0 + SPW;               // center row
        const float* rr2 = rr1 + SPW;               // row below
        #pragma unroll
        for (int j = 0; j < 4; j++) {
            float c = rr1[j + 1];
            bool k = (c >  rr0[j]) & (c >  rr0[j + 1]) & (c >  rr0[j + 2])
                   & (c >  rr1[j])
                   & (c >= rr1[j + 2])
                   & (c >= rr2[j]) & (c >= rr2[j + 1]) & (c >= rr2[j + 2]);
            mk[j] = k ? 1.0f : 0.0f;
        }
    }

    // ---------- Phase 2b: multiply all 84 channels (re-read hits L2) ----------
    {
        const float4* in = reinterpret_cast<const float4*>(pb) + off4;
        float4* op = reinterpret_cast<float4*>(out) + (size_t)b * C_ * HW4_ + off4;
        #pragma unroll 4
        for (int c = 0; c < C_; c++) {
            float4 v = in[c * HW4_];
            v.x *= mk[0];
            v.y *= mk[1];
            v.z *= mk[2];
            v.w *= mk[3];
            op[c * HW4_] = v;
        }
    }
}

extern "C" void kernel_launch(void* const* d_in, const int* in_sizes, int n_in,
                              void* d_out, int out_size) {
    const float* pts = (const float*)d_in[0];
    float* out = (float*)d_out;

    // Raise dynamic-smem limit (idempotent; not a stream-ordered op, capture-safe).
    cudaFuncSetAttribute(nms_fused_kernel,
                         cudaFuncAttributeMaxDynamicSharedMemorySize, SMEM_PAD_BYTES);

    dim3 grid(W_ / TW, H_ / TH, B_);   // (8, 32, 4); x fastest -> neighbor tiles concurrent
    nms_fused_kernel<<<grid, 256, SMEM_PAD_BYTES>>>(pts, out);
}

// round 7
// speedup vs baseline: 1.4961x; 1.4961x over previous
#include <cuda_runtime.h>
#include <cuda_bf16.h>

// points (B=4, C=84, H=512, W=512) fp32.
// probs = max over channels [0,80); 3x3 NMS, raster tie-break; out = points * mask.
//
// Two-pass, full-occupancy design:
//   A: channel-max -> g_probs (4 MB, L2-resident), 4 independent accumulators.
//   B: mask from g_probs + multiply all 84 channels. Traverses in REVERSE order
//      so its first reads hit the L2 lines kernel A touched last.

constexpr int B_  = 4;
constexpr int C_  = 84;
constexpr int CM_ = 80;
constexpr int H_  = 512;
constexpr int W_  = 512;
constexpr int HW_  = H_ * W_;
constexpr int HW4_ = HW_ / 4;     // 65536
constexpr int W4_  = W_ / 4;      // 128

__device__ float g_probs[B_ * HW_];   // 4 MB scratch

// ---------------------------------------------------------------------------
// Kernel A: probs = max over channels [0,80)
// ---------------------------------------------------------------------------
__global__ __launch_bounds__(256)
void probs_kernel(const float* __restrict__ pts) {
    int t = blockIdx.x * blockDim.x + threadIdx.x;
    int b = t >> 16;
    int o = t & (HW4_ - 1);

    const float4* base = reinterpret_cast<const float4*>(pts) + (size_t)b * C_ * HW4_ + o;

    // 4 independent accumulator chains (16 scalar chains) for MLP.
    float4 m0 = base[0];
    float4 m1 = base[HW4_];
    float4 m2 = base[2 * HW4_];
    float4 m3 = base[3 * HW4_];
    #pragma unroll 4
    for (int c = 4; c < CM_; c += 4) {
        float4 v0 = base[(size_t)(c + 0) * HW4_];
        float4 v1 = base[(size_t)(c + 1) * HW4_];
        float4 v2 = base[(size_t)(c + 2) * HW4_];
        float4 v3 = base[(size_t)(c + 3) * HW4_];
        m0.x = fmaxf(m0.x, v0.x); m0.y = fmaxf(m0.y, v0.y); m0.z = fmaxf(m0.z, v0.z); m0.w = fmaxf(m0.w, v0.w);
        m1.x = fmaxf(m1.x, v1.x); m1.y = fmaxf(m1.y, v1.y); m1.z = fmaxf(m1.z, v1.z); m1.w = fmaxf(m1.w, v1.w);
        m2.x = fmaxf(m2.x, v2.x); m2.y = fmaxf(m2.y, v2.y); m2.z = fmaxf(m2.z, v2.z); m2.w = fmaxf(m2.w, v2.w);
        m3.x = fmaxf(m3.x, v3.x); m3.y = fmaxf(m3.y, v3.y); m3.z = fmaxf(m3.z, v3.z); m3.w = fmaxf(m3.w, v3.w);
    }
    float4 m;
    m.x = fmaxf(fmaxf(m0.x, m1.x), fmaxf(m2.x, m3.x));
    m.y = fmaxf(fmaxf(m0.y, m1.y), fmaxf(m2.y, m3.y));
    m.z = fmaxf(fmaxf(m0.z, m1.z), fmaxf(m2.z, m3.z));
    m.w = fmaxf(fmaxf(m0.w, m1.w), fmaxf(m2.w, m3.w));
    reinterpret_cast<float4*>(g_probs)[(size_t)b * HW4_ + o] = m;
}

// ---------------------------------------------------------------------------
// Kernel B: NMS mask + multiply. REVERSED traversal for L2 hand-off from A.
// Tie-break (center_idx=4, 3x3 raster): strict > for positions before center,
// >= after. OOB neighbors compare vs 0.0f (zero pad).
// ---------------------------------------------------------------------------
__global__ __launch_bounds__(256)
void nms_mul_kernel(const float* __restrict__ pts, float* __restrict__ out) {
    // Reverse the global linear index so this kernel starts on the pixels
    // kernel A finished (and left in L2) last.
    int t  = (B_ * HW4_ - 1) - (blockIdx.x * blockDim.x + threadIdx.x);
    int b  = t >> 16;
    int o  = t & (HW4_ - 1);
    int h  = o >> 7;
    int w0 = (o & (W4_ - 1)) * 4;

    const float* pr = g_probs + (size_t)b * HW_;

    // 3-row x 6-col probs neighborhood (cols w0-1 .. w0+4), OOB -> 0.
    float r[3][6];
    #pragma unroll
    for (int i = 0; i < 3; i++) {
        int hh = h - 1 + i;
        bool hv = (hh >= 0) & (hh < H_);
        #pragma unroll
        for (int j = 0; j < 6; j++) {
            int ww = w0 - 1 + j;
            bool wv = (ww >= 0) & (ww < W_);
            r[i][j] = (hv & wv) ? __ldg(pr + hh * W_ + ww) : 0.0f;
        }
    }

    float m[4];
    #pragma unroll
    for (int j = 0; j < 4; j++) {
        float c = r[1][j + 1];
        bool k = (c >  r[0][j]) & (c >  r[0][j + 1]) & (c >  r[0][j + 2])
               & (c >  r[1][j])
               & (c >= r[1][j + 2])
               & (c >= r[2][j]) & (c >= r[2][j + 1]) & (c >= r[2][j + 2]);
        m[j] = k ? 1.0f : 0.0f;
    }

    size_t base = (size_t)b * C_ * HW4_ + o;
    const float4* in = reinterpret_cast<const float4*>(pts) + base;
    float4*       op = reinterpret_cast<float4*>(out) + base;
    #pragma unroll 4
    for (int c = 0; c < C_; c++) {
        float4 v = in[(size_t)c * HW4_];
        v.x *= m[0];
        v.y *= m[1];
        v.z *= m[2];
        v.w *= m[3];
        op[(size_t)c * HW4_] = v;
    }
}

extern "C" void kernel_launch(void* const* d_in, const int* in_sizes, int n_in,
                              void* d_out, int out_size) {
    const float* pts = (const float*)d_in[0];
    float* out = (float*)d_out;

    constexpr int TPB = 256;
    constexpr int BLOCKS = (B_ * HW4_) / TPB;   // 1024

    probs_kernel<<<BLOCKS, TPB>>>(pts);
    nms_mul_kernel<<<BLOCKS, TPB>>>(pts, out);
}